// round 14
// baseline (speedup 1.0000x reference)
#include <cuda_runtime.h>
#include <cuda_fp16.h>
#include <math.h>

#define B_ROWS 8192
#define N_IN   12288
#define H0     256
#define H1     32
#define H2     32
#define CAP     192
#define NWARPS  8
#define N_TILES 3072            // 384 x 8 transpose tiles (32x32 each)
#define N_UNITS (4 * B_ROWS)    // (row, color, half-scan)
#define HALF_CHUNKS 48          // 96 float4-chunks per row, 48 per unit

// Transposed fp16 feature weights: wTh[j][h]; 6.3 MB, L2-resident
__device__ __half g_wTh[N_IN * H0];
// Per-unit partial FT sums (no bias): 33.6 MB staging (L2)
__device__ float g_part[(size_t)N_UNITS * H0];
// Row completion counters + dispatch/transpose counters
__device__ unsigned g_done[B_ROWS];
__device__ int g_rowCtr, g_tpCtr, g_tpDone;

__global__ void init_state() {
    const int i = blockIdx.x * blockDim.x + threadIdx.x;
    if (i < B_ROWS) g_done[i] = 0u;
    if (i == 0) { g_rowCtr = 0; g_tpCtr = 0; g_tpDone = 0; }
}

extern __shared__ __half2 s_l1h2[];   // [p*33 + kk]: (w[kk][2p], w[kk][2p+1])

__device__ __forceinline__ float clip01(float x) {
    return fminf(fmaxf(x, 0.f), 1.f);
}

// ---------------------------------------------------------------------------
// Single fused kernel: prologue transposes ft_w (dynamic tiles, done-counter),
// then warp-autonomous (row,color,half) units with partial-sum staging.
// ---------------------------------------------------------------------------
__global__ void __launch_bounds__(256, 3)
nnue_fused(const float4* __restrict__ wfeat,
           const float4* __restrict__ bfeat,
           const unsigned int* __restrict__ side,
           const float* __restrict__ ft_w,
           const float* __restrict__ ft_b,
           const float* __restrict__ l1_w,
           const float* __restrict__ l1_b,
           const float* __restrict__ l2_w,
           const float* __restrict__ l2_b,
           const float* __restrict__ l3_w,
           const float* __restrict__ l3_b,
           float* __restrict__ out)
{
    __shared__ float s_tile[32][33];                  // transpose staging
    __shared__ float s_l2wT[H1 * 33];
    __shared__ float s_o0[NWARPS][2 * H0];
    __shared__ unsigned short s_idx[NWARPS][CAP];
    __shared__ int s_t;

    const int tid  = threadIdx.x;
    const int warp = tid >> 5;
    const int lane = tid & 31;
    const unsigned lt = (1u << lane) - 1u;

    // ---- CTA prologue A: weight caches
    for (int idx = tid; idx < H0 * H1; idx += 256) {
        const int p = idx >> 5, kk = idx & 31;
        s_l1h2[p * 33 + kk] =
            __floats2half2_rn(l1_w[kk * 2 * H0 + 2 * p], l1_w[kk * 2 * H0 + 2 * p + 1]);
    }
    for (int e = tid; e < H2 * H1; e += 256)
        s_l2wT[(e & 31) * 33 + (e >> 5)] = l2_w[e];

    float bias[8];
    #pragma unroll
    for (int q = 0; q < 4; q++) {
        bias[2 * q]     = ft_b[2 * lane + 64 * q];
        bias[2 * q + 1] = ft_b[2 * lane + 64 * q + 1];
    }
    const float l1b  = l1_b[lane];
    const float l2b  = l2_b[lane];
    const float l3w  = l3_w[lane];
    const float l3b0 = l3_b[0];
    const half2* __restrict__ wt2 = reinterpret_cast<const half2*>(g_wTh);

    // ---- CTA prologue B: cooperative transpose, dynamic 32x32 tiles
    // Tile t -> j-tile (t % 384), h-tile (t / 384). NOTE: 384 is not a power
    // of two; must use true div/mod (R13 bug: t & 383 aliased j-tiles).
    const int tx = tid & 31, ty = tid >> 5;   // (32, 8)
    for (;;) {
        if (tid == 0) s_t = atomicAdd(&g_tpCtr, 1);
        __syncthreads();
        const int t = s_t;
        if (t >= N_TILES) break;
        const int jBase = (t % 384) * 32;
        const int hB    = (t / 384) * 32;
        #pragma unroll
        for (int r = ty; r < 32; r += 8)
            s_tile[r][tx] = ft_w[(size_t)(hB + r) * N_IN + (jBase + tx)];
        __syncthreads();
        #pragma unroll
        for (int r = ty; r < 32; r += 8)
            g_wTh[(size_t)(jBase + r) * H0 + (hB + tx)] = __float2half_rn(s_tile[tx][r]);
        __threadfence();
        __syncthreads();
        if (tid == 0) atomicAdd(&g_tpDone, 1);
    }
    __syncthreads();

    unsigned short* list = s_idx[warp];
    float* o0 = s_o0[warp];
    bool wt_ready = false;

    // Stream 24 KB (48 chunks) of one color row, ballot-compact active ids.
    auto scan = [&](const float4* __restrict__ rp, int cBase) -> int {
        int n = 0;
        for (int ib = cBase; ib < cBase + HALF_CHUNKS; ib += 8) {
            float4 v[8];
            #pragma unroll
            for (int u = 0; u < 8; u++) v[u] = __ldcs(&rp[(ib + u) * 32 + lane]);
            #pragma unroll
            for (int u = 0; u < 8; u++) {
                const bool nz = (v[u].x != 0.f) | (v[u].y != 0.f) |
                                (v[u].z != 0.f) | (v[u].w != 0.f);
                if (__ballot_sync(0xffffffffu, nz) == 0u) continue;  // ~73% skip
                const int j0 = (ib + u) * 128 + 4 * lane;
                unsigned b;
                b = __ballot_sync(0xffffffffu, v[u].x != 0.f);
                if (v[u].x != 0.f) { int p = n + __popc(b & lt); if (p < CAP) list[p] = (unsigned short)j0; }
                n += __popc(b);
                b = __ballot_sync(0xffffffffu, v[u].y != 0.f);
                if (v[u].y != 0.f) { int p = n + __popc(b & lt); if (p < CAP) list[p] = (unsigned short)(j0 + 1); }
                n += __popc(b);
                b = __ballot_sync(0xffffffffu, v[u].z != 0.f);
                if (v[u].z != 0.f) { int p = n + __popc(b & lt); if (p < CAP) list[p] = (unsigned short)(j0 + 2); }
                n += __popc(b);
                b = __ballot_sync(0xffffffffu, v[u].w != 0.f);
                if (v[u].w != 0.f) { int p = n + __popc(b & lt); if (p < CAP) list[p] = (unsigned short)(j0 + 3); }
                n += __popc(b);
            }
        }
        return min(n, CAP);
    };

    auto gather = [&](int n, float* acc) {
        int k = 0;
        for (; k + 3 < n; k += 4) {
            const int b0 = (int)list[k]     * (H0 / 2) + lane;
            const int b1 = (int)list[k + 1] * (H0 / 2) + lane;
            const int b2 = (int)list[k + 2] * (H0 / 2) + lane;
            const int b3 = (int)list[k + 3] * (H0 / 2) + lane;
            #pragma unroll
            for (int q = 0; q < 4; q++) {
                float2 f0 = __half22float2(wt2[b0 + 32 * q]);
                float2 f1 = __half22float2(wt2[b1 + 32 * q]);
                float2 f2 = __half22float2(wt2[b2 + 32 * q]);
                float2 f3 = __half22float2(wt2[b3 + 32 * q]);
                acc[2 * q]     += (f0.x + f1.x) + (f2.x + f3.x);
                acc[2 * q + 1] += (f0.y + f1.y) + (f2.y + f3.y);
            }
        }
        for (; k < n; k++) {
            const int b0 = (int)list[k] * (H0 / 2) + lane;
            #pragma unroll
            for (int q = 0; q < 4; q++) {
                float2 f0 = __half22float2(wt2[b0 + 32 * q]);
                acc[2 * q]     += f0.x;
                acc[2 * q + 1] += f0.y;
            }
        }
    };

    for (;;) {
        int u;
        if (lane == 0) u = atomicAdd(&g_rowCtr, 1);
        u = __shfl_sync(0xffffffffu, u, 0);
        if (u >= N_UNITS) break;
        const int row = u >> 2;
        const int sub = u & 3;          // 0=W-lo 1=W-hi 2=B-lo 3=B-hi
        const int col = sub >> 1;

        // ---- Phase A: stream this quarter's features (DRAM), build list
        const float4* rp = (col ? bfeat : wfeat) + (size_t)row * (N_IN / 4);
        const int n = scan(rp, (sub & 1) * HALF_CHUNKS);
        __syncwarp();

        // wait (once) for the fused transpose to complete before first gather
        if (!wt_ready) {
            if (lane == 0)
                while (*(volatile int*)&g_tpDone < N_TILES) __nanosleep(64);
            __syncwarp();
            __threadfence();
            wt_ready = true;
        }

        // ---- Phase B: sparse FT gather (L2), partial sum (no bias)
        float acc[8] = {0.f, 0.f, 0.f, 0.f, 0.f, 0.f, 0.f, 0.f};
        gather(n, acc);

        // ---- Phase C: publish partial; 4th arrival finishes the row
        float* pb = &g_part[(size_t)u * H0];
        #pragma unroll
        for (int q = 0; q < 4; q++)
            __stcs(reinterpret_cast<float2*>(pb + 64 * q + 2 * lane),
                   make_float2(acc[2 * q], acc[2 * q + 1]));
        __threadfence();
        unsigned old;
        if (lane == 0) old = atomicAdd(&g_done[row], 1u);
        old = __shfl_sync(0xffffffffu, old, 0);
        if (old != 3u) continue;
        __threadfence();                // acquire: all partials visible

        // ---- Phase D0: assemble concat from the 4 partials (L2) + bias + clip
        const bool sd = (side[row] != 0u);   // int32 (1) or fp32 (0x3F800000)
        const int bw = sd ? 0 : H0;
        const int bb = sd ? H0 : 0;
        const float* p0 = &g_part[(size_t)(4 * row + 0) * H0];
        const float* p1 = &g_part[(size_t)(4 * row + 1) * H0];
        const float* p2 = &g_part[(size_t)(4 * row + 2) * H0];
        const float* p3 = &g_part[(size_t)(4 * row + 3) * H0];
        #pragma unroll
        for (int q = 0; q < 4; q++) {
            const int h = 64 * q + 2 * lane;
            const float2 a = __ldcg(reinterpret_cast<const float2*>(p0 + h));
            const float2 b = __ldcg(reinterpret_cast<const float2*>(p1 + h));
            const float2 c = __ldcg(reinterpret_cast<const float2*>(p2 + h));
            const float2 d = __ldcg(reinterpret_cast<const float2*>(p3 + h));
            o0[bw + h]     = clip01(a.x + b.x + bias[2 * q]);
            o0[bw + h + 1] = clip01(a.y + b.y + bias[2 * q + 1]);
            o0[bb + h]     = clip01(c.x + d.x + bias[2 * q]);
            o0[bb + h + 1] = clip01(c.y + d.y + bias[2 * q + 1]);
        }
        __syncwarp();

        // ---- Phase D: l1 (lane = output unit; fp16 weights, fp32 accum)
        float s = l1b;
        const float4* o04 = reinterpret_cast<const float4*>(o0);
        #pragma unroll 8
        for (int pp = 0; pp < (2 * H0) / 4; pp++) {
            const float4 ov = o04[pp];
            const float2 w0 = __half22float2(s_l1h2[(2 * pp)     * 33 + lane]);
            const float2 w1 = __half22float2(s_l1h2[(2 * pp + 1) * 33 + lane]);
            s += ov.x * w0.x + ov.y * w0.y + ov.z * w1.x + ov.w * w1.y;
        }
        const float o1 = clip01(s);

        // ---- Phase E: l2 via shfl broadcast, then l3 + sigmoid
        float s2 = l2b;
        #pragma unroll
        for (int i = 0; i < H1; i++)
            s2 += __shfl_sync(0xffffffffu, o1, i) * s_l2wT[i * 33 + lane];
        const float o2 = clip01(s2);

        float p = o2 * l3w;
        #pragma unroll
        for (int o = 16; o; o >>= 1) p += __shfl_xor_sync(0xffffffffu, p, o);
        if (lane == 0)
            out[row] = 1.f / (1.f + expf(-1.5f * (p + l3b0)));   // 300/200

        __syncwarp();   // o0/list reuse safety before next unit
    }
}

// ---------------------------------------------------------------------------
extern "C" void kernel_launch(void* const* d_in, const int* in_sizes, int n_in,
                              void* d_out, int out_size) {
    const float*        wfeat = (const float*)d_in[0];
    const float*        bfeat = (const float*)d_in[1];
    const unsigned int* side  = (const unsigned int*)d_in[2];
    const float*        ft_w  = (const float*)d_in[3];
    const float*        ft_b  = (const float*)d_in[4];
    const float*        l1_w  = (const float*)d_in[5];
    const float*        l1_b  = (const float*)d_in[6];
    const float*        l2_w  = (const float*)d_in[7];
    const float*        l2_b  = (const float*)d_in[8];
    const float*        l3_w  = (const float*)d_in[9];
    const float*        l3_b  = (const float*)d_in[10];
    float* out = (float*)d_out;

    // K1: reset all counters (~1us)
    init_state<<<(B_ROWS + 255) / 256, 256>>>();

    // K2: single fused kernel (transpose prologue + NNUE), 456 = 3 x 152 SMs
    const int dyn_smem = H0 * 33 * (int)sizeof(__half2);   // 33792
    cudaFuncSetAttribute(nnue_fused, cudaFuncAttributeMaxDynamicSharedMemorySize, dyn_smem);
    nnue_fused<<<456, 256, dyn_smem>>>(
        (const float4*)wfeat, (const float4*)bfeat, side, ft_w,
        ft_b, l1_w, l1_b, l2_w, l2_b, l3_w, l3_b, out);
}